// round 10
// baseline (speedup 1.0000x reference)
#include <cuda_runtime.h>
#include <cuda_bf16.h>
#include <math.h>
#include <stdint.h>

#define N_NODES 100000
#define IN_CH 128
#define HID 256
#define EMB 128
#define N_PAIRS 500000

__device__ float g_z[(size_t)N_NODES * EMB];
__device__ float g_u[(size_t)N_NODES * HID];   // Z @ SW1[0:128]
__device__ float g_v[(size_t)N_NODES * HID];   // Z @ SW1[128:256]
// SW1^T bf16: 8 blocks (seg*2+half) of (hi,lo) tiles, 32768 elems (64KB) each, swizzled
__device__ __align__(16) __nv_bfloat16 g_w1[8 * 32768];
// SW2^T bf16: 2 blocks (khalf) of (hi,lo) tiles, 32768 elems each
__device__ __align__(16) __nv_bfloat16 g_w2[2 * 32768];

__device__ __forceinline__ float4 ld4(const float* p) { return *reinterpret_cast<const float4*>(p); }
__device__ __forceinline__ void st4(float* p, float4 v) { *reinterpret_cast<float4*>(p) = v; }

typedef unsigned long long u64;
__device__ __forceinline__ u64 fma2(u64 a, u64 b, u64 c) {
    u64 d; asm("fma.rn.f32x2 %0, %1, %2, %3;" : "=l"(d) : "l"(a), "l"(b), "l"(c)); return d;
}
__device__ __forceinline__ u64 dup2(float f) {
    u64 d; unsigned u = __float_as_uint(f);
    asm("mov.b64 %0, {%1, %1};" : "=l"(d) : "r"(u)); return d;
}
__device__ __forceinline__ float2 unpk(u64 v) {
    float2 r; asm("mov.b64 {%0, %1}, %2;" : "=f"(r.x), "=f"(r.y) : "l"(v)); return r;
}

__device__ __forceinline__ uint32_t smem_u32(const void* p) { return (uint32_t)__cvta_generic_to_shared(p); }

// pack (a -> low bf16, b -> high bf16)
__device__ __forceinline__ uint32_t pk_hi(float a, float b) {
    uint32_t r; asm("cvt.rn.bf16x2.f32 %0, %1, %2;" : "=r"(r) : "f"(b), "f"(a)); return r;
}
__device__ __forceinline__ uint32_t pk_lo(float a, float b, uint32_t h) {
    float ah = __uint_as_float(h << 16);
    float bh = __uint_as_float(h & 0xFFFF0000u);
    return pk_hi(a - ah, b - bh);
}

#define STS128(addr, r) asm volatile("st.shared.v4.b32 [%0], {%1,%2,%3,%4};" \
    :: "r"(addr), "r"((r)[0]), "r"((r)[1]), "r"((r)[2]), "r"((r)[3]) : "memory")
#define STS32(addr, v) asm volatile("st.shared.b32 [%0], %1;" :: "r"(addr), "r"(v) : "memory")
#define CP_COMMIT() asm volatile("cp.async.commit_group;" ::: "memory")
#define CP_WAIT(n)  asm volatile("cp.async.wait_group %0;" :: "n"(n) : "memory")

__device__ __forceinline__ void cpa16(uint32_t dst, const void* src) {
    asm volatile("cp.async.cg.shared.global [%0], [%1], 16;" :: "r"(dst), "l"(src) : "memory");
}
__device__ __forceinline__ void ldsm4(uint32_t* r, uint32_t addr) {
    asm volatile("ldmatrix.sync.aligned.m8n8.x4.shared.b16 {%0,%1,%2,%3}, [%4];"
        : "=r"(r[0]), "=r"(r[1]), "=r"(r[2]), "=r"(r[3]) : "r"(addr));
}
__device__ __forceinline__ void mma16816(float* c, const uint32_t* a, uint32_t b0, uint32_t b1) {
    asm volatile("mma.sync.aligned.m16n8k16.row.col.f32.bf16.bf16.f32 "
        "{%0,%1,%2,%3}, {%4,%5,%6,%7}, {%8,%9}, {%0,%1,%2,%3};"
        : "+f"(c[0]), "+f"(c[1]), "+f"(c[2]), "+f"(c[3])
        : "r"(a[0]), "r"(a[1]), "r"(a[2]), "r"(a[3]), "r"(b0), "r"(b1));
}

// smem layout (bytes from dynamic base)
#define SB0_OFF   0
#define SB1_OFF   65536
#define SA1H_OFF  131072
#define SA1L_OFF  163840
#define SA2H_OFF  65536
#define SA2L_OFF  131072
#define CST_OFF   196608
#define SMEM_SZ   202752

// ---------------------------------------------------------------------------
// prep: split + transpose weights into swizzled bf16 tiles
// tile = [128 n][128 k]; byteoff = n*256 + (((k>>3) ^ (n&7))<<4) + (k&7)*2
// ---------------------------------------------------------------------------
__global__ void prep_kernel(const float* __restrict__ SW1, const float* __restrict__ SW2)
{
    int idx = blockIdx.x * 256 + threadIdx.x;
    if (idx < 8 * 32768) {
        int blk = idx >> 15;              // seg*2 + half
        int e = idx & 32767;
        int prec = e >> 14;               // 0 = hi, 1 = lo
        int n = (e >> 7) & 127, k = e & 127;
        int seg = blk >> 1, half = blk & 1;
        float w = SW1[(seg * 128 + k) * 256 + half * 128 + n];
        __nv_bfloat16 h = __float2bfloat16(w);
        __nv_bfloat16 v = prec ? __float2bfloat16(w - __bfloat162float(h)) : h;
        int off = n * 256 + (((k >> 3) ^ (n & 7)) << 4) + (k & 7) * 2;
        g_w1[blk * 32768 + prec * 16384 + (off >> 1)] = v;
    } else if (idx < 8 * 32768 + 2 * 32768) {
        int i2 = idx - 8 * 32768;
        int blk = i2 >> 15;               // khalf
        int e = i2 & 32767;
        int prec = e >> 14;
        int n = (e >> 7) & 127, k = e & 127;
        float w = SW2[(blk * 128 + k) * 128 + n];
        __nv_bfloat16 h = __float2bfloat16(w);
        __nv_bfloat16 v = prec ? __float2bfloat16(w - __bfloat162float(h)) : h;
        int off = n * 256 + (((k >> 3) ^ (n & 7)) << 4) + (k & 7) * 2;
        g_w2[blk * 32768 + prec * 16384 + (off >> 1)] = v;
    }
}

// ---------------------------------------------------------------------------
// Node kernel (FFMA2, unchanged from R4)
// ---------------------------------------------------------------------------
__global__ __launch_bounds__(256, 2) void node_kernel(
    const float* __restrict__ x, const float* __restrict__ xm, const float* __restrict__ xsd,
    const float* __restrict__ W1, const float* __restrict__ b1,
    const float* __restrict__ bng, const float* __restrict__ bnb,
    const float* __restrict__ bnm, const float* __restrict__ bnv,
    const float* __restrict__ W2, const float* __restrict__ b2)
{
    extern __shared__ float sm[];
    float* xsT = sm;
    float* hs  = sm + IN_CH * 64;
    const int t = threadIdx.x;
    const int nb0 = blockIdx.x * 64;
    {
        const int nn = t & 63;
        const int node = nb0 + nn;
        const bool ok = node < N_NODES;
        #pragma unroll
        for (int it = 0; it < 8; it++) {
            int c4 = (t >> 6) + 4 * it;
            float4 v = make_float4(0.f, 0.f, 0.f, 0.f);
            if (ok) v = ld4(x + (size_t)node * IN_CH + 4 * c4);
            float4 m = ld4(xm + 4 * c4), s = ld4(xsd + 4 * c4);
            float a;
            a = isfinite(v.x) ? v.x : 0.f; a = (a - m.x) / s.x; xsT[(4*c4+0)*64+nn] = fminf(fmaxf(a,-10.f),10.f);
            a = isfinite(v.y) ? v.y : 0.f; a = (a - m.y) / s.y; xsT[(4*c4+1)*64+nn] = fminf(fmaxf(a,-10.f),10.f);
            a = isfinite(v.z) ? v.z : 0.f; a = (a - m.z) / s.z; xsT[(4*c4+2)*64+nn] = fminf(fmaxf(a,-10.f),10.f);
            a = isfinite(v.w) ? v.w : 0.f; a = (a - m.w) / s.w; xsT[(4*c4+3)*64+nn] = fminf(fmaxf(a,-10.f),10.f);
        }
    }
    __syncthreads();
    {
        const int cg = t & 63, ng = t >> 6;
        u64 acc[8][4];
        #pragma unroll
        for (int pp = 0; pp < 8; pp++) { acc[pp][0]=acc[pp][1]=acc[pp][2]=acc[pp][3]=0ull; }
        const float* xcol = xsT + ng * 16;
        #pragma unroll 2
        for (int k = 0; k < IN_CH; k++) {
            u64 a2[8];
            const ulonglong2* sp = reinterpret_cast<const ulonglong2*>(xcol + k * 64);
            #pragma unroll
            for (int q = 0; q < 4; q++) { ulonglong2 v = sp[q]; a2[2*q] = v.x; a2[2*q+1] = v.y; }
            float4 w = ld4(W1 + k * HID + 4 * cg);
            u64 wx = dup2(w.x), wy = dup2(w.y), wz = dup2(w.z), ww = dup2(w.w);
            #pragma unroll
            for (int pp = 0; pp < 8; pp++) {
                acc[pp][0] = fma2(a2[pp], wx, acc[pp][0]);
                acc[pp][1] = fma2(a2[pp], wy, acc[pp][1]);
                acc[pp][2] = fma2(a2[pp], wz, acc[pp][2]);
                acc[pp][3] = fma2(a2[pp], ww, acc[pp][3]);
            }
        }
        float4 bb = ld4(b1 + 4 * cg), gg = ld4(bng + 4 * cg), be = ld4(bnb + 4 * cg);
        float4 mm = ld4(bnm + 4 * cg), vv = ld4(bnv + 4 * cg);
        float4 sc, off;
        sc.x = gg.x * rsqrtf(vv.x + 1e-5f); off.x = be.x + (bb.x - mm.x) * sc.x;
        sc.y = gg.y * rsqrtf(vv.y + 1e-5f); off.y = be.y + (bb.y - mm.y) * sc.y;
        sc.z = gg.z * rsqrtf(vv.z + 1e-5f); off.z = be.z + (bb.z - mm.z) * sc.z;
        sc.w = gg.w * rsqrtf(vv.w + 1e-5f); off.w = be.w + (bb.w - mm.w) * sc.w;
        #pragma unroll
        for (int pp = 0; pp < 8; pp++) {
            float2 e0 = unpk(acc[pp][0]), e1 = unpk(acc[pp][1]);
            float2 e2 = unpk(acc[pp][2]), e3 = unpk(acc[pp][3]);
            float4 h0, h1;
            h0.x = fmaxf(e0.x * sc.x + off.x, 0.f); h1.x = fmaxf(e0.y * sc.x + off.x, 0.f);
            h0.y = fmaxf(e1.x * sc.y + off.y, 0.f); h1.y = fmaxf(e1.y * sc.y + off.y, 0.f);
            h0.z = fmaxf(e2.x * sc.z + off.z, 0.f); h1.z = fmaxf(e2.y * sc.z + off.z, 0.f);
            h0.w = fmaxf(e3.x * sc.w + off.w, 0.f); h1.w = fmaxf(e3.y * sc.w + off.w, 0.f);
            st4(hs + (ng * 16 + 2*pp + 0) * HID + 4 * cg, h0);
            st4(hs + (ng * 16 + 2*pp + 1) * HID + 4 * cg, h1);
        }
    }
    __syncthreads();
    {
        const int cg = t & 31, ng = t >> 5;
        u64 acc[8][2];
        #pragma unroll
        for (int p = 0; p < 8; p++) { acc[p][0] = acc[p][1] = 0ull; }
        const float* hrow = hs + ng * 8 * HID;
        #pragma unroll 2
        for (int k = 0; k < HID; k++) {
            ulonglong2 wv = *reinterpret_cast<const ulonglong2*>(W2 + k * EMB + 4 * cg);
            #pragma unroll
            for (int p = 0; p < 8; p++) {
                u64 a = dup2(hrow[p * HID + k]);
                acc[p][0] = fma2(a, wv.x, acc[p][0]);
                acc[p][1] = fma2(a, wv.y, acc[p][1]);
            }
        }
        float4 bb = ld4(b2 + 4 * cg);
        #pragma unroll
        for (int p = 0; p < 8; p++) {
            int node = nb0 + ng * 8 + p;
            if (node < N_NODES) {
                float2 e0 = unpk(acc[p][0]), e1 = unpk(acc[p][1]);
                float4 r;
                r.x = fmaxf(e0.x + bb.x, 0.f); r.y = fmaxf(e0.y + bb.y, 0.f);
                r.z = fmaxf(e1.x + bb.z, 0.f); r.w = fmaxf(e1.y + bb.w, 0.f);
                st4(g_z + (size_t)node * EMB + 4 * cg, r);
            }
        }
    }
}

// ---------------------------------------------------------------------------
// Shared MMA machinery (16 warps; warp (mg, nq) covers rows mg*16.., cols nq*64..)
// ---------------------------------------------------------------------------
__device__ __forceinline__ void loadB(uint32_t dst, const __nv_bfloat16* src, int t) {
    for (int j = t; j < 4096; j += 512) cpa16(dst + j * 16, src + j * 8);
}

// one K=128 pass over a 64-col quarter: A [astride B/row], B [256B rows]
__device__ __forceinline__ void mma_pass(float (&C)[8][4], uint32_t sAh, uint32_t sAl,
                                         uint32_t sBh, uint32_t sBl,
                                         int lane, int m0, int nq64, int astride, int kcbase) {
    int tile = lane >> 3, rr = lane & 7;
    int ra = m0 + ((tile & 1) << 3) + rr;
    int rbn = ((tile >> 1) << 3) + rr;
    for (int k0 = 0; k0 < 128; k0 += 16) {
        int kcA = kcbase + (k0 >> 3) + (tile >> 1);
        uint32_t aoff = ra * astride + ((kcA ^ rr) << 4);
        uint32_t ah[4], al[4];
        ldsm4(ah, sAh + aoff);
        ldsm4(al, sAl + aoff);
        int kcB = (k0 >> 3) + (tile & 1);
        #pragma unroll
        for (int np = 0; np < 4; np++) {
            int n = nq64 + np * 16 + rbn;
            uint32_t boff = n * 256 + ((kcB ^ rr) << 4);
            uint32_t bh[4], bl[4];
            ldsm4(bh, sBh + boff);
            ldsm4(bl, sBl + boff);
            mma16816(C[2*np],   ah, bh[0], bh[1]);
            mma16816(C[2*np+1], ah, bh[2], bh[3]);
            mma16816(C[2*np],   al, bh[0], bh[1]);
            mma16816(C[2*np+1], al, bh[2], bh[3]);
            mma16816(C[2*np],   ah, bl[0], bl[1]);
            mma16816(C[2*np+1], ah, bl[2], bl[3]);
        }
    }
}

// ---------------------------------------------------------------------------
// uv_kernel: U = Z @ SW1[0:128], V = Z @ SW1[128:256] over 100k nodes.
// Reuses g_w1 blocks 0..3 (seg0 half0/1, seg1 half0/1) and the mma machinery.
// ---------------------------------------------------------------------------
__global__ __launch_bounds__(512) void uv_kernel()
{
    extern __shared__ char smraw[];
    const uint32_t base = smem_u32(smraw);
    const uint32_t SB0 = base + SB0_OFF, SB1 = base + SB1_OFF;
    const uint32_t SAH = base + SA1H_OFF, SAL = base + SA1L_OFF;
    const int t = threadIdx.x;
    const int lane = t & 31;
    const int wid = t >> 5;
    const int m0 = (wid >> 1) * 16;
    const int nq64 = (wid & 1) * 64;
    const int p0 = blockIdx.x * 128;

    // build A (z rows, bf16 hi/lo, swizzled)
    {
        int r = t & 127, kq = t >> 7;
        int node = p0 + r; if (node >= N_NODES) node = N_NODES - 1;
        const float* zr = g_z + (size_t)node * 128 + kq * 32;
        #pragma unroll
        for (int c = 0; c < 4; c++) {
            int kc = kq * 4 + c;
            float4 v0 = ld4(zr + c * 8), v1 = ld4(zr + c * 8 + 4);
            float f[8] = {v0.x, v0.y, v0.z, v0.w, v1.x, v1.y, v1.z, v1.w};
            uint32_t hi[4], lo[4];
            #pragma unroll
            for (int i = 0; i < 4; i++) {
                hi[i] = pk_hi(f[2*i], f[2*i+1]);
                lo[i] = pk_lo(f[2*i], f[2*i+1], hi[i]);
            }
            uint32_t off = r * 256 + (((kc ^ (r & 7))) << 4);
            STS128(SAH + off, hi);
            STS128(SAL + off, lo);
        }
    }
    loadB(SB0, g_w1, t);
    CP_COMMIT();
    __syncthreads();

    for (int ps = 0; ps < 4; ps++) {
        __syncthreads();
        if (ps < 3) {
            loadB(((ps + 1) & 1) ? SB1 : SB0, g_w1 + (size_t)(ps + 1) * 32768, t);
            CP_COMMIT();
            CP_WAIT(1);
        } else {
            CP_WAIT(0);
        }
        __syncthreads();
        float C[8][4];
        #pragma unroll
        for (int i = 0; i < 8; i++) {
            #pragma unroll
            for (int j = 0; j < 4; j++) C[i][j] = 0.f;
        }
        uint32_t sb = (ps & 1) ? SB1 : SB0;
        mma_pass(C, SAH, SAL, sb, sb + 32768, lane, m0, nq64, 256, 0);
        float* dst = (ps < 2) ? g_u : g_v;
        int colb = (ps & 1) * 128;
        int r0 = m0 + (lane >> 2), r1 = r0 + 8;
        int n0g = p0 + r0, n1g = p0 + r1;
        #pragma unroll
        for (int nt = 0; nt < 8; nt++) {
            int n = colb + nq64 + nt * 8 + (lane & 3) * 2;
            if (n0g < N_NODES) {
                dst[(size_t)n0g * HID + n]     = C[nt][0];
                dst[(size_t)n0g * HID + n + 1] = C[nt][1];
            }
            if (n1g < N_NODES) {
                dst[(size_t)n1g * HID + n]     = C[nt][2];
                dst[(size_t)n1g * HID + n + 1] = C[nt][3];
            }
        }
    }
}

// ---------------------------------------------------------------------------
// Pair kernel: only nonlinear segments (src*dst, |src-dst|) through MMA;
// linear seg0/seg1 contributions gathered from precomputed U/V in the epilogue.
// ---------------------------------------------------------------------------
__device__ __forceinline__ void buildA1(int seg, int t, uint32_t sAh, uint32_t sAl,
                                        const int* si, const int* di) {
    int r = t & 127, kq = t >> 7;   // kq = 0..3, each covers 32 k-cols
    const float* zs = g_z + (size_t)si[r] * 128 + kq * 32;
    const float* zd = g_z + (size_t)di[r] * 128 + kq * 32;
    #pragma unroll
    for (int c = 0; c < 4; c++) {
        int kc = kq * 4 + c;
        float f[8];
        float4 s0 = ld4(zs + c * 8), s1 = ld4(zs + c * 8 + 4);
        float4 d0 = ld4(zd + c * 8), d1 = ld4(zd + c * 8 + 4);
        float ss[8] = {s0.x,s0.y,s0.z,s0.w,s1.x,s1.y,s1.z,s1.w};
        float dd[8] = {d0.x,d0.y,d0.z,d0.w,d1.x,d1.y,d1.z,d1.w};
        if (seg == 2) {
            #pragma unroll
            for (int i = 0; i < 8; i++) f[i] = ss[i] * dd[i];
        } else {
            #pragma unroll
            for (int i = 0; i < 8; i++) f[i] = fabsf(ss[i] - dd[i]);
        }
        uint32_t hi[4], lo[4];
        #pragma unroll
        for (int i = 0; i < 4; i++) {
            hi[i] = pk_hi(f[2*i], f[2*i+1]);
            lo[i] = pk_lo(f[2*i], f[2*i+1], hi[i]);
        }
        uint32_t off = r * 256 + (((kc ^ (r & 7))) << 4);
        STS128(sAh + off, hi);
        STS128(sAl + off, lo);
    }
}

__global__ __launch_bounds__(512) void pair_mma_kernel(
    const int* __restrict__ ep, const float* __restrict__ ldeg,
    const float* __restrict__ SW1, const float* __restrict__ Sb1,
    const float* __restrict__ Sb2, const float* __restrict__ SW3,
    const float* __restrict__ Sb3, float* __restrict__ out)
{
    extern __shared__ char smraw[];
    const uint32_t base = smem_u32(smraw);
    const uint32_t SB0 = base + SB0_OFF, SB1 = base + SB1_OFF;
    const uint32_t SA1H = base + SA1H_OFF, SA1L = base + SA1L_OFF;
    const uint32_t SA2H = base + SA2H_OFF, SA2L = base + SA2L_OFF;
    float* cst = (float*)(smraw + CST_OFF);        // b1[256] w512[256] w513[256] b2[128] w3[128]
    float* sdg = cst + 1024;
    float* ddg = cst + 1152;
    int* si = (int*)(cst + 1280);                  // reused as GEMM3 partials later
    int* di = (int*)(cst + 1408);
    float* part = (float*)(cst + 1280);            // [2][128], valid after epilogue done

    const int t = threadIdx.x;
    const int lane = t & 31;
    const int wid = t >> 5;
    const int m0 = (wid >> 1) * 16;    // m-group
    const int nq64 = (wid & 1) * 64;   // n-quarter within current 128-col B tile
    const int p0 = blockIdx.x * 128;

    for (int i = t; i < 1024; i += 512) {
        float v;
        if (i < 256) v = Sb1[i];
        else if (i < 512) v = SW1[512 * 256 + (i - 256)];
        else if (i < 768) v = SW1[513 * 256 + (i - 512)];
        else if (i < 896) v = Sb2[i - 768];
        else v = SW3[i - 896];
        cst[i] = v;
    }
    if (t < 128) {
        int p = p0 + t;
        int pv = p < N_PAIRS ? p : 0;
        int s = ep[2 * (size_t)pv], d = ep[2 * (size_t)pv + 1];
        si[t] = s; di[t] = d;
        sdg[t] = ldeg[s]; ddg[t] = ldeg[d];
    }
    __syncthreads();

    loadB(SB0, g_w1 + (size_t)4 * 32768, t);   // seg2 half0
    CP_COMMIT();

    float C1a[8][4], C1b[8][4];
    #pragma unroll
    for (int i = 0; i < 8; i++) {
        #pragma unroll
        for (int j = 0; j < 4; j++) { C1a[i][j] = 0.f; C1b[i][j] = 0.f; }
    }

    for (int it = 0; it < 4; it++) {
        int seg = 2 + (it >> 1), half = it & 1;
        __syncthreads();
        if (it < 3) loadB(((it + 1) & 1) ? SB1 : SB0, g_w1 + (size_t)(5 + it) * 32768, t);
        else        loadB(SB0, g_w2, t);     // prefetch B2 khalf0
        CP_COMMIT();
        if (half == 0) buildA1(seg, t, SA1H, SA1L, si, di);
        CP_WAIT(1);
        __syncthreads();
        uint32_t sb = (it & 1) ? SB1 : SB0;
        if (half == 0) mma_pass(C1a, SA1H, SA1L, sb, sb + 32768, lane, m0, nq64, 256, 0);
        else           mma_pass(C1b, SA1H, SA1L, sb, sb + 32768, lane, m0, nq64, 256, 0);
    }
    __syncthreads();    // all GEMM1 mma done before overwriting SA2 region

    // epilogue: s1 = relu(C1 + U[si] + V[di] + b1 + sdeg*w512 + ddeg*w513) -> bf16 hi/lo
    {
        const float* cb1 = cst;
        const float* w5 = cst + 256;
        const float* w6 = cst + 512;
        int r0 = m0 + (lane >> 2), r1 = r0 + 8;
        float sd0 = sdg[r0], dd0 = ddg[r0], sd1 = sdg[r1], dd1 = ddg[r1];
        const float* U0 = g_u + (size_t)si[r0] * HID;
        const float* V0 = g_v + (size_t)di[r0] * HID;
        const float* U1 = g_u + (size_t)si[r1] * HID;
        const float* V1 = g_v + (size_t)di[r1] * HID;
        #define EPI_HALF(CARR, HALF) do { \
            _Pragma("unroll") \
            for (int nt = 0; nt < 8; nt++) { \
                int n = (HALF) * 128 + nq64 + nt * 8 + (lane & 3) * 2; \
                float v00 = fmaxf(CARR[nt][0] + U0[n]   + V0[n]   + cb1[n]   + sd0 * w5[n]   + dd0 * w6[n],   0.f); \
                float v01 = fmaxf(CARR[nt][1] + U0[n+1] + V0[n+1] + cb1[n+1] + sd0 * w5[n+1] + dd0 * w6[n+1], 0.f); \
                float v10 = fmaxf(CARR[nt][2] + U1[n]   + V1[n]   + cb1[n]   + sd1 * w5[n]   + dd1 * w6[n],   0.f); \
                float v11 = fmaxf(CARR[nt][3] + U1[n+1] + V1[n+1] + cb1[n+1] + sd1 * w5[n+1] + dd1 * w6[n+1], 0.f); \
                uint32_t h0 = pk_hi(v00, v01), l0 = pk_lo(v00, v01, h0); \
                uint32_t h1 = pk_hi(v10, v11), l1 = pk_lo(v10, v11, h1); \
                int kc = n >> 3; int ib = (n & 7) * 2; \
                uint32_t o0 = r0 * 512 + ((kc ^ (r0 & 7)) << 4) + ib; \
                uint32_t o1 = r1 * 512 + ((kc ^ (r1 & 7)) << 4) + ib; \
                STS32(SA2H + o0, h0); STS32(SA2L + o0, l0); \
                STS32(SA2H + o1, h1); STS32(SA2L + o1, l1); \
            } } while (0)
        EPI_HALF(C1a, 0);
        EPI_HALF(C1b, 1);
        #undef EPI_HALF
    }
    CP_WAIT(0);
    __syncthreads();

    float C2[8][4];
    #pragma unroll
    for (int i = 0; i < 8; i++) {
        #pragma unroll
        for (int j = 0; j < 4; j++) C2[i][j] = 0.f;
    }

    mma_pass(C2, SA2H, SA2L, SB0, SB0 + 32768, lane, m0, nq64, 512, 0);
    __syncthreads();
    loadB(SB0, g_w2 + 32768, t);
    CP_COMMIT(); CP_WAIT(0);
    __syncthreads();
    mma_pass(C2, SA2H, SA2L, SB0, SB0 + 32768, lane, m0, nq64, 512, 16);

    // GEMM3: relu(s2 + b2) . w3 per row; partial per n-quarter, combine via smem
    {
        const float* cb2 = cst + 768;
        const float* cw3 = cst + 896;
        float a0 = 0.f, a1 = 0.f;
        #pragma unroll
        for (int nt = 0; nt < 8; nt++) {
            int n = nq64 + nt * 8 + (lane & 3) * 2;
            a0 += fmaxf(C2[nt][0] + cb2[n], 0.f) * cw3[n] + fmaxf(C2[nt][1] + cb2[n+1], 0.f) * cw3[n+1];
            a1 += fmaxf(C2[nt][2] + cb2[n], 0.f) * cw3[n] + fmaxf(C2[nt][3] + cb2[n+1], 0.f) * cw3[n+1];
        }
        a0 += __shfl_xor_sync(0xffffffffu, a0, 1); a0 += __shfl_xor_sync(0xffffffffu, a0, 2);
        a1 += __shfl_xor_sync(0xffffffffu, a1, 1); a1 += __shfl_xor_sync(0xffffffffu, a1, 2);
        __syncthreads();   // si/di reads done; safe to reuse as partials
        if ((lane & 3) == 0) {
            int r0 = m0 + (lane >> 2), r1 = r0 + 8;
            int q = (nq64 != 0) ? 128 : 0;
            part[q + r0] = a0;
            part[q + r1] = a1;
        }
        __syncthreads();
        if (t < 128) {
            float l = part[t] + part[128 + t] + Sb3[0];
            if (isnan(l)) l = 0.f;
            else if (isinf(l)) l = (l > 0.f) ? 20.f : -20.f;
            if (p0 + t < N_PAIRS) out[p0 + t] = l;
        }
    }
}

extern "C" void kernel_launch(void* const* d_in, const int* in_sizes, int n_in,
                              void* d_out, int out_size)
{
    const float* x    = (const float*)d_in[0];
    const int*   ep   = (const int*)d_in[2];
    const float* xm   = (const float*)d_in[3];
    const float* xsd  = (const float*)d_in[4];
    const float* ldeg = (const float*)d_in[5];
    const float* W1   = (const float*)d_in[6];
    const float* b1   = (const float*)d_in[7];
    const float* bng  = (const float*)d_in[8];
    const float* bnb  = (const float*)d_in[9];
    const float* bnm  = (const float*)d_in[10];
    const float* bnv  = (const float*)d_in[11];
    const float* W2   = (const float*)d_in[12];
    const float* b2   = (const float*)d_in[13];
    const float* SW1  = (const float*)d_in[14];
    const float* Sb1  = (const float*)d_in[15];
    const float* SW2  = (const float*)d_in[16];
    const float* Sb2  = (const float*)d_in[17];
    const float* SW3  = (const float*)d_in[18];
    const float* Sb3  = (const float*)d_in[19];
    float* out = (float*)d_out;

    cudaFuncSetAttribute(node_kernel, cudaFuncAttributeMaxDynamicSharedMemorySize, 98304);
    cudaFuncSetAttribute(uv_kernel, cudaFuncAttributeMaxDynamicSharedMemorySize, SMEM_SZ);
    cudaFuncSetAttribute(pair_mma_kernel, cudaFuncAttributeMaxDynamicSharedMemorySize, SMEM_SZ);

    prep_kernel<<<1280, 256>>>(SW1, SW2);
    node_kernel<<<(N_NODES + 63) / 64, 256, 98304>>>(x, xm, xsd, W1, b1, bng, bnb, bnm, bnv, W2, b2);
    uv_kernel<<<(N_NODES + 127) / 128, 512, SMEM_SZ>>>();
    pair_mma_kernel<<<(N_PAIRS + 127) / 128, 512, SMEM_SZ>>>(ep, ldeg, SW1, Sb1, Sb2, SW3, Sb3, out);
}

// round 11
// speedup vs baseline: 1.5123x; 1.5123x over previous
#include <cuda_runtime.h>
#include <cuda_fp16.h>
#include <math.h>
#include <stdint.h>

#define N_NODES 100000
#define IN_CH 128
#define HID 256
#define EMB 128
#define N_PAIRS 500000

__device__ float g_z[(size_t)N_NODES * EMB];
__device__ float g_u[(size_t)N_NODES * HID];   // Z @ SW1[0:128]
__device__ float g_v[(size_t)N_NODES * HID];   // Z @ SW1[128:256]
// SW1^T fp16: 8 blocks (seg*2+half), each [128n x 128k] swizzled = 16384 elems (32KB)
__device__ __align__(16) __half g_w1[8 * 16384];
// SW2^T fp16: 2 blocks (khalf), 16384 elems each
__device__ __align__(16) __half g_w2[2 * 16384];

__device__ __forceinline__ float4 ld4(const float* p) { return *reinterpret_cast<const float4*>(p); }
__device__ __forceinline__ void st4(float* p, float4 v) { *reinterpret_cast<float4*>(p) = v; }

typedef unsigned long long u64;
__device__ __forceinline__ u64 fma2(u64 a, u64 b, u64 c) {
    u64 d; asm("fma.rn.f32x2 %0, %1, %2, %3;" : "=l"(d) : "l"(a), "l"(b), "l"(c)); return d;
}
__device__ __forceinline__ u64 dup2(float f) {
    u64 d; unsigned u = __float_as_uint(f);
    asm("mov.b64 %0, {%1, %1};" : "=l"(d) : "r"(u)); return d;
}
__device__ __forceinline__ float2 unpk(u64 v) {
    float2 r; asm("mov.b64 {%0, %1}, %2;" : "=f"(r.x), "=f"(r.y) : "l"(v)); return r;
}

__device__ __forceinline__ uint32_t smem_u32(const void* p) { return (uint32_t)__cvta_generic_to_shared(p); }

// pack (a -> low f16, b -> high f16)
__device__ __forceinline__ uint32_t pk16(float a, float b) {
    uint32_t r; asm("cvt.rn.f16x2.f32 %0, %1, %2;" : "=r"(r) : "f"(b), "f"(a)); return r;
}

#define STS128(addr, r) asm volatile("st.shared.v4.b32 [%0], {%1,%2,%3,%4};" \
    :: "r"(addr), "r"((r)[0]), "r"((r)[1]), "r"((r)[2]), "r"((r)[3]) : "memory")
#define STS32(addr, v) asm volatile("st.shared.b32 [%0], %1;" :: "r"(addr), "r"(v) : "memory")
#define CP_COMMIT() asm volatile("cp.async.commit_group;" ::: "memory")
#define CP_WAIT(n)  asm volatile("cp.async.wait_group %0;" :: "n"(n) : "memory")

__device__ __forceinline__ void cpa16(uint32_t dst, const void* src) {
    asm volatile("cp.async.cg.shared.global [%0], [%1], 16;" :: "r"(dst), "l"(src) : "memory");
}
__device__ __forceinline__ void ldsm4(uint32_t* r, uint32_t addr) {
    asm volatile("ldmatrix.sync.aligned.m8n8.x4.shared.b16 {%0,%1,%2,%3}, [%4];"
        : "=r"(r[0]), "=r"(r[1]), "=r"(r[2]), "=r"(r[3]) : "r"(addr));
}
__device__ __forceinline__ void mma16816(float* c, const uint32_t* a, uint32_t b0, uint32_t b1) {
    asm volatile("mma.sync.aligned.m16n8k16.row.col.f32.f16.f16.f32 "
        "{%0,%1,%2,%3}, {%4,%5,%6,%7}, {%8,%9}, {%0,%1,%2,%3};"
        : "+f"(c[0]), "+f"(c[1]), "+f"(c[2]), "+f"(c[3])
        : "r"(a[0]), "r"(a[1]), "r"(a[2]), "r"(a[3]), "r"(b0), "r"(b1));
}

// smem layout (bytes from dynamic base)
#define SB0_OFF   0
#define SB1_OFF   32768
#define SA1_OFF   65536     // GEMM1 A tile: [128 rows][128k fp16] = 32KB
#define SA2_OFF   98304     // GEMM2 A tile: [128 rows][256k fp16] = 64KB
#define CST_OFF   163840
#define SMEM_SZ   170240

// ---------------------------------------------------------------------------
// prep: transpose weights into swizzled fp16 tiles
// tile = [128 n][128 k]; byteoff = n*256 + (((k>>3) ^ (n&7))<<4) + (k&7)*2
// ---------------------------------------------------------------------------
__global__ void prep_kernel(const float* __restrict__ SW1, const float* __restrict__ SW2)
{
    int idx = blockIdx.x * 256 + threadIdx.x;
    if (idx < 8 * 16384) {
        int blk = idx >> 14;              // seg*2 + half
        int e = idx & 16383;
        int n = e >> 7, k = e & 127;
        int seg = blk >> 1, half = blk & 1;
        float w = SW1[(seg * 128 + k) * 256 + half * 128 + n];
        int off = n * 256 + (((k >> 3) ^ (n & 7)) << 4) + (k & 7) * 2;
        g_w1[blk * 16384 + (off >> 1)] = __float2half(w);
    } else if (idx < 8 * 16384 + 2 * 16384) {
        int i2 = idx - 8 * 16384;
        int blk = i2 >> 14;               // khalf
        int e = i2 & 16383;
        int n = e >> 7, k = e & 127;
        float w = SW2[(blk * 128 + k) * 128 + n];
        int off = n * 256 + (((k >> 3) ^ (n & 7)) << 4) + (k & 7) * 2;
        g_w2[blk * 16384 + (off >> 1)] = __float2half(w);
    }
}

// ---------------------------------------------------------------------------
// Node kernel (FFMA2, unchanged from R4)
// ---------------------------------------------------------------------------
__global__ __launch_bounds__(256, 2) void node_kernel(
    const float* __restrict__ x, const float* __restrict__ xm, const float* __restrict__ xsd,
    const float* __restrict__ W1, const float* __restrict__ b1,
    const float* __restrict__ bng, const float* __restrict__ bnb,
    const float* __restrict__ bnm, const float* __restrict__ bnv,
    const float* __restrict__ W2, const float* __restrict__ b2)
{
    extern __shared__ float sm[];
    float* xsT = sm;
    float* hs  = sm + IN_CH * 64;
    const int t = threadIdx.x;
    const int nb0 = blockIdx.x * 64;
    {
        const int nn = t & 63;
        const int node = nb0 + nn;
        const bool ok = node < N_NODES;
        #pragma unroll
        for (int it = 0; it < 8; it++) {
            int c4 = (t >> 6) + 4 * it;
            float4 v = make_float4(0.f, 0.f, 0.f, 0.f);
            if (ok) v = ld4(x + (size_t)node * IN_CH + 4 * c4);
            float4 m = ld4(xm + 4 * c4), s = ld4(xsd + 4 * c4);
            float a;
            a = isfinite(v.x) ? v.x : 0.f; a = (a - m.x) / s.x; xsT[(4*c4+0)*64+nn] = fminf(fmaxf(a,-10.f),10.f);
            a = isfinite(v.y) ? v.y : 0.f; a = (a - m.y) / s.y; xsT[(4*c4+1)*64+nn] = fminf(fmaxf(a,-10.f),10.f);
            a = isfinite(v.z) ? v.z : 0.f; a = (a - m.z) / s.z; xsT[(4*c4+2)*64+nn] = fminf(fmaxf(a,-10.f),10.f);
            a = isfinite(v.w) ? v.w : 0.f; a = (a - m.w) / s.w; xsT[(4*c4+3)*64+nn] = fminf(fmaxf(a,-10.f),10.f);
        }
    }
    __syncthreads();
    {
        const int cg = t & 63, ng = t >> 6;
        u64 acc[8][4];
        #pragma unroll
        for (int pp = 0; pp < 8; pp++) { acc[pp][0]=acc[pp][1]=acc[pp][2]=acc[pp][3]=0ull; }
        const float* xcol = xsT + ng * 16;
        #pragma unroll 2
        for (int k = 0; k < IN_CH; k++) {
            u64 a2[8];
            const ulonglong2* sp = reinterpret_cast<const ulonglong2*>(xcol + k * 64);
            #pragma unroll
            for (int q = 0; q < 4; q++) { ulonglong2 v = sp[q]; a2[2*q] = v.x; a2[2*q+1] = v.y; }
            float4 w = ld4(W1 + k * HID + 4 * cg);
            u64 wx = dup2(w.x), wy = dup2(w.y), wz = dup2(w.z), ww = dup2(w.w);
            #pragma unroll
            for (int pp = 0; pp < 8; pp++) {
                acc[pp][0] = fma2(a2[pp], wx, acc[pp][0]);
                acc[pp][1] = fma2(a2[pp], wy, acc[pp][1]);
                acc[pp][2] = fma2(a2[pp], wz, acc[pp][2]);
                acc[pp][3] = fma2(a2[pp], ww, acc[pp][3]);
            }
        }
        float4 bb = ld4(b1 + 4 * cg), gg = ld4(bng + 4 * cg), be = ld4(bnb + 4 * cg);
        float4 mm = ld4(bnm + 4 * cg), vv = ld4(bnv + 4 * cg);
        float4 sc, off;
        sc.x = gg.x * rsqrtf(vv.x + 1e-5f); off.x = be.x + (bb.x - mm.x) * sc.x;
        sc.y = gg.y * rsqrtf(vv.y + 1e-5f); off.y = be.y + (bb.y - mm.y) * sc.y;
        sc.z = gg.z * rsqrtf(vv.z + 1e-5f); off.z = be.z + (bb.z - mm.z) * sc.z;
        sc.w = gg.w * rsqrtf(vv.w + 1e-5f); off.w = be.w + (bb.w - mm.w) * sc.w;
        #pragma unroll
        for (int pp = 0; pp < 8; pp++) {
            float2 e0 = unpk(acc[pp][0]), e1 = unpk(acc[pp][1]);
            float2 e2 = unpk(acc[pp][2]), e3 = unpk(acc[pp][3]);
            float4 h0, h1;
            h0.x = fmaxf(e0.x * sc.x + off.x, 0.f); h1.x = fmaxf(e0.y * sc.x + off.x, 0.f);
            h0.y = fmaxf(e1.x * sc.y + off.y, 0.f); h1.y = fmaxf(e1.y * sc.y + off.y, 0.f);
            h0.z = fmaxf(e2.x * sc.z + off.z, 0.f); h1.z = fmaxf(e2.y * sc.z + off.z, 0.f);
            h0.w = fmaxf(e3.x * sc.w + off.w, 0.f); h1.w = fmaxf(e3.y * sc.w + off.w, 0.f);
            st4(hs + (ng * 16 + 2*pp + 0) * HID + 4 * cg, h0);
            st4(hs + (ng * 16 + 2*pp + 1) * HID + 4 * cg, h1);
        }
    }
    __syncthreads();
    {
        const int cg = t & 31, ng = t >> 5;
        u64 acc[8][2];
        #pragma unroll
        for (int p = 0; p < 8; p++) { acc[p][0] = acc[p][1] = 0ull; }
        const float* hrow = hs + ng * 8 * HID;
        #pragma unroll 2
        for (int k = 0; k < HID; k++) {
            ulonglong2 wv = *reinterpret_cast<const ulonglong2*>(W2 + k * EMB + 4 * cg);
            #pragma unroll
            for (int p = 0; p < 8; p++) {
                u64 a = dup2(hrow[p * HID + k]);
                acc[p][0] = fma2(a, wv.x, acc[p][0]);
                acc[p][1] = fma2(a, wv.y, acc[p][1]);
            }
        }
        float4 bb = ld4(b2 + 4 * cg);
        #pragma unroll
        for (int p = 0; p < 8; p++) {
            int node = nb0 + ng * 8 + p;
            if (node < N_NODES) {
                float2 e0 = unpk(acc[p][0]), e1 = unpk(acc[p][1]);
                float4 r;
                r.x = fmaxf(e0.x + bb.x, 0.f); r.y = fmaxf(e0.y + bb.y, 0.f);
                r.z = fmaxf(e1.x + bb.z, 0.f); r.w = fmaxf(e1.y + bb.w, 0.f);
                st4(g_z + (size_t)node * EMB + 4 * cg, r);
            }
        }
    }
}

// ---------------------------------------------------------------------------
// Shared MMA machinery (16 warps; warp (mg, nq) covers rows mg*16.., cols nq*64..)
// ---------------------------------------------------------------------------
__device__ __forceinline__ void loadB(uint32_t dst, const __half* src, int t) {
    for (int j = t; j < 2048; j += 512) cpa16(dst + j * 16, src + j * 8);
}

// one K=128 pass over a 64-col quarter: A [astride B/row], B [256B rows], fp16 single
__device__ __forceinline__ void mma_pass(float (&C)[8][4], uint32_t sA, uint32_t sB,
                                         int lane, int m0, int nq64, int astride, int kcbase) {
    int tile = lane >> 3, rr = lane & 7;
    int ra = m0 + ((tile & 1) << 3) + rr;
    int rbn = ((tile >> 1) << 3) + rr;
    for (int k0 = 0; k0 < 128; k0 += 16) {
        int kcA = kcbase + (k0 >> 3) + (tile >> 1);
        uint32_t ah[4];
        ldsm4(ah, sA + ra * astride + ((kcA ^ rr) << 4));
        int kcB = (k0 >> 3) + (tile & 1);
        #pragma unroll
        for (int np = 0; np < 4; np++) {
            int n = nq64 + np * 16 + rbn;
            uint32_t bh[4];
            ldsm4(bh, sB + n * 256 + ((kcB ^ rr) << 4));
            mma16816(C[2*np],   ah, bh[0], bh[1]);
            mma16816(C[2*np+1], ah, bh[2], bh[3]);
        }
    }
}

// ---------------------------------------------------------------------------
// uv_kernel: U = Z @ SW1[0:128], V = Z @ SW1[128:256] over 100k nodes.
// ---------------------------------------------------------------------------
__global__ __launch_bounds__(512) void uv_kernel()
{
    extern __shared__ char smraw[];
    const uint32_t base = smem_u32(smraw);
    const uint32_t SB0 = base + SB0_OFF, SB1 = base + SB1_OFF;
    const uint32_t SA = base + SA1_OFF;
    const int t = threadIdx.x;
    const int lane = t & 31;
    const int wid = t >> 5;
    const int m0 = (wid >> 1) * 16;
    const int nq64 = (wid & 1) * 64;
    const int p0 = blockIdx.x * 128;

    // build A (z rows, fp16, swizzled)
    {
        int r = t & 127, kq = t >> 7;
        int node = p0 + r; if (node >= N_NODES) node = N_NODES - 1;
        const float* zr = g_z + (size_t)node * 128 + kq * 32;
        #pragma unroll
        for (int c = 0; c < 4; c++) {
            int kc = kq * 4 + c;
            float4 v0 = ld4(zr + c * 8), v1 = ld4(zr + c * 8 + 4);
            uint32_t hi[4];
            hi[0] = pk16(v0.x, v0.y); hi[1] = pk16(v0.z, v0.w);
            hi[2] = pk16(v1.x, v1.y); hi[3] = pk16(v1.z, v1.w);
            STS128(SA + r * 256 + (((kc ^ (r & 7))) << 4), hi);
        }
    }
    loadB(SB0, g_w1, t);
    CP_COMMIT();
    __syncthreads();

    for (int ps = 0; ps < 4; ps++) {
        __syncthreads();
        if (ps < 3) {
            loadB(((ps + 1) & 1) ? SB1 : SB0, g_w1 + (size_t)(ps + 1) * 16384, t);
            CP_COMMIT();
            CP_WAIT(1);
        } else {
            CP_WAIT(0);
        }
        __syncthreads();
        float C[8][4];
        #pragma unroll
        for (int i = 0; i < 8; i++) {
            #pragma unroll
            for (int j = 0; j < 4; j++) C[i][j] = 0.f;
        }
        uint32_t sb = (ps & 1) ? SB1 : SB0;
        mma_pass(C, SA, sb, lane, m0, nq64, 256, 0);
        float* dst = (ps < 2) ? g_u : g_v;
        int colb = (ps & 1) * 128;
        int r0 = m0 + (lane >> 2), r1 = r0 + 8;
        int n0g = p0 + r0, n1g = p0 + r1;
        #pragma unroll
        for (int nt = 0; nt < 8; nt++) {
            int n = colb + nq64 + nt * 8 + (lane & 3) * 2;
            if (n0g < N_NODES) {
                dst[(size_t)n0g * HID + n]     = C[nt][0];
                dst[(size_t)n0g * HID + n + 1] = C[nt][1];
            }
            if (n1g < N_NODES) {
                dst[(size_t)n1g * HID + n]     = C[nt][2];
                dst[(size_t)n1g * HID + n + 1] = C[nt][3];
            }
        }
    }
}

// ---------------------------------------------------------------------------
// Pair kernel: nonlinear segments (src*dst, |src-dst|) through fp16 MMA;
// linear contributions gathered from precomputed U/V in the epilogue.
// ---------------------------------------------------------------------------
__device__ __forceinline__ void buildA1(int seg, int t, uint32_t sA,
                                        const int* si, const int* di) {
    int r = t & 127, kq = t >> 7;   // kq = 0..3, each covers 32 k-cols
    const float* zs = g_z + (size_t)si[r] * 128 + kq * 32;
    const float* zd = g_z + (size_t)di[r] * 128 + kq * 32;
    #pragma unroll
    for (int c = 0; c < 4; c++) {
        int kc = kq * 4 + c;
        float4 s0 = ld4(zs + c * 8), s1 = ld4(zs + c * 8 + 4);
        float4 d0 = ld4(zd + c * 8), d1 = ld4(zd + c * 8 + 4);
        float ss[8] = {s0.x,s0.y,s0.z,s0.w,s1.x,s1.y,s1.z,s1.w};
        float dd[8] = {d0.x,d0.y,d0.z,d0.w,d1.x,d1.y,d1.z,d1.w};
        float f[8];
        if (seg == 2) {
            #pragma unroll
            for (int i = 0; i < 8; i++) f[i] = ss[i] * dd[i];
        } else {
            #pragma unroll
            for (int i = 0; i < 8; i++) f[i] = fabsf(ss[i] - dd[i]);
        }
        uint32_t hi[4];
        #pragma unroll
        for (int i = 0; i < 4; i++) hi[i] = pk16(f[2*i], f[2*i+1]);
        STS128(sA + r * 256 + (((kc ^ (r & 7))) << 4), hi);
    }
}

__global__ __launch_bounds__(512) void pair_mma_kernel(
    const int* __restrict__ ep, const float* __restrict__ ldeg,
    const float* __restrict__ SW1, const float* __restrict__ Sb1,
    const float* __restrict__ Sb2, const float* __restrict__ SW3,
    const float* __restrict__ Sb3, float* __restrict__ out)
{
    extern __shared__ char smraw[];
    const uint32_t base = smem_u32(smraw);
    const uint32_t SB0 = base + SB0_OFF, SB1 = base + SB1_OFF;
    const uint32_t SA1 = base + SA1_OFF, SA2 = base + SA2_OFF;
    float* cst = (float*)(smraw + CST_OFF);        // b1[256] w512[256] w513[256] b2[128] w3[128]
    float* sdg = cst + 1024;
    float* ddg = cst + 1152;
    int* si = (int*)(cst + 1280);                  // reused as GEMM3 partials later
    int* di = (int*)(cst + 1408);
    float* part = (float*)(cst + 1280);            // [2][128], valid after epilogue done

    const int t = threadIdx.x;
    const int lane = t & 31;
    const int wid = t >> 5;
    const int m0 = (wid >> 1) * 16;    // m-group
    const int nq64 = (wid & 1) * 64;   // n-quarter within current 128-col B tile
    const int p0 = blockIdx.x * 128;

    for (int i = t; i < 1024; i += 512) {
        float v;
        if (i < 256) v = Sb1[i];
        else if (i < 512) v = SW1[512 * 256 + (i - 256)];
        else if (i < 768) v = SW1[513 * 256 + (i - 512)];
        else if (i < 896) v = Sb2[i - 768];
        else v = SW3[i - 896];
        cst[i] = v;
    }
    if (t < 128) {
        int p = p0 + t;
        int pv = p < N_PAIRS ? p : 0;
        int s = ep[2 * (size_t)pv], d = ep[2 * (size_t)pv + 1];
        si[t] = s; di[t] = d;
        sdg[t] = ldeg[s]; ddg[t] = ldeg[d];
    }
    __syncthreads();

    loadB(SB0, g_w1 + (size_t)4 * 16384, t);   // seg2 half0
    CP_COMMIT();

    float C1a[8][4], C1b[8][4];
    #pragma unroll
    for (int i = 0; i < 8; i++) {
        #pragma unroll
        for (int j = 0; j < 4; j++) { C1a[i][j] = 0.f; C1b[i][j] = 0.f; }
    }

    for (int it = 0; it < 4; it++) {
        int seg = 2 + (it >> 1), half = it & 1;
        __syncthreads();
        if (it < 3) loadB(((it + 1) & 1) ? SB1 : SB0, g_w1 + (size_t)(5 + it) * 16384, t);
        else        loadB(SB0, g_w2, t);     // prefetch B2 khalf0
        CP_COMMIT();
        if (half == 0) buildA1(seg, t, SA1, si, di);
        CP_WAIT(1);
        __syncthreads();
        uint32_t sb = (it & 1) ? SB1 : SB0;
        if (half == 0) mma_pass(C1a, SA1, sb, lane, m0, nq64, 256, 0);
        else           mma_pass(C1b, SA1, sb, lane, m0, nq64, 256, 0);
    }
    __syncthreads();    // all GEMM1 mma done

    // epilogue: s1 = relu(C1 + U[si] + V[di] + b1 + sdeg*w512 + ddeg*w513) -> fp16 into SA2
    {
        const float* cb1 = cst;
        const float* w5 = cst + 256;
        const float* w6 = cst + 512;
        int r0 = m0 + (lane >> 2), r1 = r0 + 8;
        float sd0 = sdg[r0], dd0 = ddg[r0], sd1 = sdg[r1], dd1 = ddg[r1];
        const float* U0 = g_u + (size_t)si[r0] * HID;
        const float* V0 = g_v + (size_t)di[r0] * HID;
        const float* U1 = g_u + (size_t)si[r1] * HID;
        const float* V1 = g_v + (size_t)di[r1] * HID;
        #define EPI_HALF(CARR, HALF) do { \
            _Pragma("unroll") \
            for (int nt = 0; nt < 8; nt++) { \
                int n = (HALF) * 128 + nq64 + nt * 8 + (lane & 3) * 2; \
                float v00 = fmaxf(CARR[nt][0] + U0[n]   + V0[n]   + cb1[n]   + sd0 * w5[n]   + dd0 * w6[n],   0.f); \
                float v01 = fmaxf(CARR[nt][1] + U0[n+1] + V0[n+1] + cb1[n+1] + sd0 * w5[n+1] + dd0 * w6[n+1], 0.f); \
                float v10 = fmaxf(CARR[nt][2] + U1[n]   + V1[n]   + cb1[n]   + sd1 * w5[n]   + dd1 * w6[n],   0.f); \
                float v11 = fmaxf(CARR[nt][3] + U1[n+1] + V1[n+1] + cb1[n+1] + sd1 * w5[n+1] + dd1 * w6[n+1], 0.f); \
                uint32_t h0 = pk16(v00, v01); \
                uint32_t h1 = pk16(v10, v11); \
                int kc = n >> 3; int ib = (n & 7) * 2; \
                STS32(SA2 + r0 * 512 + ((kc ^ (r0 & 7)) << 4) + ib, h0); \
                STS32(SA2 + r1 * 512 + ((kc ^ (r1 & 7)) << 4) + ib, h1); \
            } } while (0)
        EPI_HALF(C1a, 0);
        EPI_HALF(C1b, 1);
        #undef EPI_HALF
    }
    CP_WAIT(0);
    __syncthreads();

    float C2[8][4];
    #pragma unroll
    for (int i = 0; i < 8; i++) {
        #pragma unroll
        for (int j = 0; j < 4; j++) C2[i][j] = 0.f;
    }

    mma_pass(C2, SA2, SB0, lane, m0, nq64, 512, 0);
    __syncthreads();
    loadB(SB0, g_w2 + 16384, t);
    CP_COMMIT(); CP_WAIT(0);
    __syncthreads();
    mma_pass(C2, SA2, SB0, lane, m0, nq64, 512, 16);

    // GEMM3: relu(s2 + b2) . w3 per row; partial per n-quarter, combine via smem
    {
        const float* cb2 = cst + 768;
        const float* cw3 = cst + 896;
        float a0 = 0.f, a1 = 0.f;
        #pragma unroll
        for (int nt = 0; nt < 8; nt++) {
            int n = nq64 + nt * 8 + (lane & 3) * 2;
            a0 += fmaxf(C2[nt][0] + cb2[n], 0.f) * cw3[n] + fmaxf(C2[nt][1] + cb2[n+1], 0.f) * cw3[n+1];
            a1 += fmaxf(C2[nt][2] + cb2[n], 0.f) * cw3[n] + fmaxf(C2[nt][3] + cb2[n+1], 0.f) * cw3[n+1];
        }
        a0 += __shfl_xor_sync(0xffffffffu, a0, 1); a0 += __shfl_xor_sync(0xffffffffu, a0, 2);
        a1 += __shfl_xor_sync(0xffffffffu, a1, 1); a1 += __shfl_xor_sync(0xffffffffu, a1, 2);
        __syncthreads();   // si/di reads done; safe to reuse as partials
        if ((lane & 3) == 0) {
            int r0 = m0 + (lane >> 2), r1 = r0 + 8;
            int q = (nq64 != 0) ? 128 : 0;
            part[q + r0] = a0;
            part[q + r1] = a1;
        }
        __syncthreads();
        if (t < 128) {
            float l = part[t] + part[128 + t] + Sb3[0];
            if (isnan(l)) l = 0.f;
            else if (isinf(l)) l = (l > 0.f) ? 20.f : -20.f;
            if (p0 + t < N_PAIRS) out[p0 + t] = l;
        }
    }
}

extern "C" void kernel_launch(void* const* d_in, const int* in_sizes, int n_in,
                              void* d_out, int out_size)
{
    const float* x    = (const float*)d_in[0];
    const int*   ep   = (const int*)d_in[2];
    const float* xm   = (const float*)d_in[3];
    const float* xsd  = (const float*)d_in[4];
    const float* ldeg = (const float*)d_in[5];
    const float* W1   = (const float*)d_in[6];
    const float* b1   = (const float*)d_in[7];
    const float* bng  = (const float*)d_in[8];
    const float* bnb  = (const float*)d_in[9];
    const float* bnm  = (const float*)d_in[10];
    const float* bnv  = (const float*)d_in[11];
    const float* W2   = (const float*)d_in[12];
    const float* b2   = (const float*)d_in[13];
    const float* SW1  = (const float*)d_in[14];
    const float* Sb1  = (const float*)d_in[15];
    const float* SW2  = (const float*)d_in[16];
    const float* Sb2  = (const float*)d_in[17];
    const float* SW3  = (const float*)d_in[18];
    const float* Sb3  = (const float*)d_in[19];
    float* out = (float*)d_out;

    cudaFuncSetAttribute(node_kernel, cudaFuncAttributeMaxDynamicSharedMemorySize, 98304);
    cudaFuncSetAttribute(uv_kernel, cudaFuncAttributeMaxDynamicSharedMemorySize, SMEM_SZ);
    cudaFuncSetAttribute(pair_mma_kernel, cudaFuncAttributeMaxDynamicSharedMemorySize, SMEM_SZ);

    prep_kernel<<<640, 256>>>(SW1, SW2);
    node_kernel<<<(N_NODES + 63) / 64, 256, 98304>>>(x, xm, xsd, W1, b1, bng, bnb, bnm, bnv, W2, b2);
    uv_kernel<<<(N_NODES + 127) / 128, 512, SMEM_SZ>>>();
    pair_mma_kernel<<<(N_PAIRS + 127) / 128, 512, SMEM_SZ>>>(ep, ldeg, SW1, Sb1, Sb2, SW3, Sb3, out);
}